// round 16
// baseline (speedup 1.0000x reference)
#include <cuda_runtime.h>
#include <cuda_fp16.h>
#include <math.h>
#include <stdint.h>

#define EMBED   2048
#define NHEADS  16
#define NKV     4
#define HDIM    128
#define BATCH   2
#define SEQ     2048
#define NTOK    (BATCH*SEQ)      // 4096
#define KVDIM   1024             // k(512) + v(512)
#define QKVN    (EMBED + KVDIM)  // 3072 fused projection width

// fp16 scratch
__device__ __half g_xh   [NTOK * EMBED];
__device__ __half g_wh   [QKVN * EMBED];    // Wq rows 0..2047, Wkv rows 2048..3071
__device__ __half g_woh  [EMBED * EMBED];
__device__ __half g_qkv16[NTOK * QKVN];     // fused projection out (pre-rope)
__device__ __half g_qh   [NTOK * EMBED];    // [b][h][s][d], rope'd + scaled*log2e
__device__ __half g_kh   [NTOK * 512];      // [b][kvh][s][d], rope'd
__device__ __half g_vh   [NTOK * 512];      // [b][kvh][s][d]
__device__ __half g_oh   [NTOK * EMBED];    // attention out (token-major)
// aux
__device__ float2 g_rope_tab[SEQ * 64];     // (cos, sin) per (s, i)
__device__ float  g_bqkv[QKVN];             // stacked bias

// ---------------------------------------------------------------------------
// PTX helpers (baseline sm_80+ features only)
// ---------------------------------------------------------------------------
__device__ __forceinline__ uint32_t smem_to_u32(const void* p) {
    uint32_t a;
    asm("{ .reg .u64 t; cvta.to.shared.u64 t, %1; cvt.u32.u64 %0, t; }" : "=r"(a) : "l"(p));
    return a;
}

__device__ __forceinline__ void mma16(float c[4], const uint32_t a[4], const uint32_t b[2]) {
    asm volatile(
        "mma.sync.aligned.m16n8k16.row.col.f32.f16.f16.f32 "
        "{%0,%1,%2,%3},{%4,%5,%6,%7},{%8,%9},{%0,%1,%2,%3};"
        : "+f"(c[0]), "+f"(c[1]), "+f"(c[2]), "+f"(c[3])
        : "r"(a[0]), "r"(a[1]), "r"(a[2]), "r"(a[3]), "r"(b[0]), "r"(b[1]));
}

__device__ __forceinline__ void ldsm4(uint32_t r[4], uint32_t addr) {
    asm volatile("ldmatrix.sync.aligned.m8n8.x4.shared.b16 {%0,%1,%2,%3}, [%4];"
        : "=r"(r[0]), "=r"(r[1]), "=r"(r[2]), "=r"(r[3]) : "r"(addr));
}

__device__ __forceinline__ void ldsm4t(uint32_t r[4], uint32_t addr) {
    asm volatile("ldmatrix.sync.aligned.m8n8.x4.trans.shared.b16 {%0,%1,%2,%3}, [%4];"
        : "=r"(r[0]), "=r"(r[1]), "=r"(r[2]), "=r"(r[3]) : "r"(addr));
}

__device__ __forceinline__ void cp16(uint32_t dst, const void* src) {
    asm volatile("cp.async.cg.shared.global [%0], [%1], 16;" :: "r"(dst), "l"(src));
}
#define CP_COMMIT() asm volatile("cp.async.commit_group;" ::: "memory")
#define CP_WAIT0()  asm volatile("cp.async.wait_group 0;" ::: "memory")
#define CP_WAIT1()  asm volatile("cp.async.wait_group 1;" ::: "memory")
#define CP_WAIT2()  asm volatile("cp.async.wait_group 2;" ::: "memory")

__device__ __forceinline__ float ex2f(float x) {
    float r; asm("ex2.approx.f32 %0, %1;" : "=f"(r) : "f"(x)); return r;
}
__device__ __forceinline__ uint32_t h2exp2u(uint32_t x) {
    uint32_t r; asm("ex2.approx.f16x2 %0, %1;" : "=r"(r) : "r"(x)); return r;
}
__device__ __forceinline__ uint32_t pack_h2(float a, float b) {
    __half2 h = __floats2half2_rn(a, b);
    return *(uint32_t*)&h;
}

// ---------------------------------------------------------------------------
// Fused prep: fp32->fp16 of x, Wq|Wkv (packed), Wo; RoPE table; stacked bias.
// ---------------------------------------------------------------------------
__global__ void prep_all(const float4* __restrict__ x,  const float4* __restrict__ wq,
                         const float4* __restrict__ wkv, const float4* __restrict__ wo,
                         const float* __restrict__ bq,  const float* __restrict__ bkv)
{
    const int n_x   = NTOK * EMBED / 4;
    const int n_wq  = EMBED * EMBED / 4;
    const int n_wkv = KVDIM * EMBED / 4;
    const int n_wo  = EMBED * EMBED / 4;
    const int n_tab = SEQ * 64;
    int i = blockIdx.x * blockDim.x + threadIdx.x;

    int base = 0;
    if (i < (base += n_x)) {
        int j = i;
        float4 v = x[j];
        __half2 h0 = __floats2half2_rn(v.x, v.y), h1 = __floats2half2_rn(v.z, v.w);
        ((uint2*)g_xh)[j] = make_uint2(*(uint32_t*)&h0, *(uint32_t*)&h1);
    } else if (i < (base += n_wq)) {
        int j = i - (base - n_wq);
        float4 v = wq[j];
        __half2 h0 = __floats2half2_rn(v.x, v.y), h1 = __floats2half2_rn(v.z, v.w);
        ((uint2*)g_wh)[j] = make_uint2(*(uint32_t*)&h0, *(uint32_t*)&h1);
    } else if (i < (base += n_wkv)) {
        int j = i - (base - n_wkv);
        float4 v = wkv[j];
        __half2 h0 = __floats2half2_rn(v.x, v.y), h1 = __floats2half2_rn(v.z, v.w);
        ((uint2*)(g_wh + (size_t)EMBED * EMBED))[j] = make_uint2(*(uint32_t*)&h0, *(uint32_t*)&h1);
    } else if (i < (base += n_wo)) {
        int j = i - (base - n_wo);
        float4 v = wo[j];
        __half2 h0 = __floats2half2_rn(v.x, v.y), h1 = __floats2half2_rn(v.z, v.w);
        ((uint2*)g_woh)[j] = make_uint2(*(uint32_t*)&h0, *(uint32_t*)&h1);
    } else if (i < (base += n_tab)) {
        int j = i - (base - n_tab);
        int s = j >> 6, d = j & 63;
        float freq = powf(10000.0f, -(float)d * (1.0f / 64.0f));
        float sn, cs; sincosf((float)s * freq, &sn, &cs);
        g_rope_tab[j] = make_float2(cs, sn);
    } else if (i < (base += QKVN)) {
        int j = i - (base - QKVN);
        g_bqkv[j] = (j < EMBED) ? bq[j] : bkv[j - EMBED];
    }
}

// ---------------------------------------------------------------------------
// GEMM: C[M,N] = A[M,K](fp16) @ W[N,K]^T(fp16) + bias.  HOUT: fp16 vs fp32 C.
// CTA 256x128, BK=64, 8 warps each 64x64 (mma:ldsm = 4.0), 4-stage cp.async,
// single sync per k-tile. Stage = A(36864)+B(18432) = 55296 B; x4 = 221184 B.
// 1 CTA/SM; pipeline depth + 32 indep accumulator frags hide latency.
// ---------------------------------------------------------------------------
template <bool HOUT>
__global__ __launch_bounds__(256, 1) void gemm_h(
    const __half* __restrict__ A, const __half* __restrict__ W,
    const float* __restrict__ bias, void* __restrict__ Cout,
    int M, int N, int K)
{
    extern __shared__ char smc[];
    const uint32_t sb = smem_to_u32(smc);

    const int bm   = blockIdx.y * 256;
    const int bn   = blockIdx.x * 128;
    const int tid  = threadIdx.x;
    const int lane = tid & 31;
    const int w    = tid >> 5;
    const int mw   = w & 3;      // 4 strips of 64 rows
    const int nw   = w >> 2;     // 2 strips of 64 cols
    const int lr   = lane >> 2;
    const int lc   = lane & 3;

    float acc[4][8][4];
#pragma unroll
    for (int mi = 0; mi < 4; mi++)
#pragma unroll
        for (int ni = 0; ni < 8; ni++)
#pragma unroll
            for (int c = 0; c < 4; c++) acc[mi][ni][c] = 0.f;

    const int NT = K / 64;

    auto issue = [&](int t) {
        const int buf = t & 3;
        const int kb  = t * 64;
        uint32_t abuf = sb + buf * 55296;
        uint32_t bbuf = abuf + 36864;
#pragma unroll
        for (int i = 0; i < 8; i++) {            // A: 256 rows
            int slot = tid + i * 256;            // 0..2047
            int r = slot >> 3, c = slot & 7;
            cp16(abuf + r * 144 + c * 16, A + (size_t)(bm + r) * K + kb + c * 8);
        }
#pragma unroll
        for (int i = 0; i < 4; i++) {            // B: 128 rows
            int slot = tid + i * 256;            // 0..1023
            int r = slot >> 3, c = slot & 7;
            cp16(bbuf + r * 144 + c * 16, W + (size_t)(bn + r) * K + kb + c * 8);
        }
        CP_COMMIT();
    };

    const uint32_t a_base = sb + (mw * 64 + (lane & 15)) * 144 + (lane >> 4) * 16;
    const uint32_t b_base = sb + 36864
        + (nw * 64 + ((lane >> 4) << 3) + (lane & 7)) * 144 + ((lane >> 3) & 1) * 16;

    issue(0);
    issue(1);
    issue(2);

    for (int t = 0; t < NT; t++) {
        if (t + 2 < NT)      { CP_WAIT2(); }
        else if (t + 1 < NT) { CP_WAIT1(); }
        else                 { CP_WAIT0(); }
        __syncthreads();               // buf t ready; all warps past compute(t-1)
        if (t + 3 < NT) issue(t + 3);  // overwrites buf (t-1)&3 — safe post-sync

        const uint32_t boff = (t & 3) * 55296;
#pragma unroll
        for (int ks = 0; ks < 4; ks++) {
            uint32_t af[4][4];
#pragma unroll
            for (int mi = 0; mi < 4; mi++)
                ldsm4(af[mi], a_base + boff + mi * 2304 + ks * 32);
#pragma unroll
            for (int np = 0; np < 4; np++) {
                uint32_t bf[4];
                ldsm4(bf, b_base + boff + np * 2304 + ks * 32);
#pragma unroll
                for (int mi = 0; mi < 4; mi++) {
                    mma16(acc[mi][np * 2],     af[mi], bf);
                    mma16(acc[mi][np * 2 + 1], af[mi], bf + 2);
                }
            }
        }
    }

    // Epilogue
#pragma unroll
    for (int mi = 0; mi < 4; mi++) {
        int r = bm + mw * 64 + mi * 16 + lr;
#pragma unroll
        for (int ni = 0; ni < 8; ni++) {
            int cc = bn + nw * 64 + ni * 8 + 2 * lc;
            float b0 = bias ? bias[cc] : 0.f;
            float b1 = bias ? bias[cc + 1] : 0.f;
            float v00 = acc[mi][ni][0] + b0, v01 = acc[mi][ni][1] + b1;
            float v10 = acc[mi][ni][2] + b0, v11 = acc[mi][ni][3] + b1;
            if (HOUT) {
                __half* C = (__half*)Cout;
                __half2 h0 = __floats2half2_rn(v00, v01);
                __half2 h1 = __floats2half2_rn(v10, v11);
                *(__half2*)(C + (size_t)r * N + cc)       = h0;
                *(__half2*)(C + (size_t)(r + 8) * N + cc) = h1;
            } else {
                float* C = (float*)Cout;
                *(float2*)(C + (size_t)r * N + cc)       = make_float2(v00, v01);
                *(float2*)(C + (size_t)(r + 8) * N + cc) = make_float2(v10, v11);
            }
        }
    }
}

// ---------------------------------------------------------------------------
// RoPE + repack. Q scaled by (1/sqrt(128))*log2(e) for base-2 softmax.
// ---------------------------------------------------------------------------
__global__ void rope_h()
{
    const int QTOT = NTOK * NHEADS * 64;
    const int KTOT = NTOK * NKV * 64;
    const int VTOT = NTOK * NKV * 64;
    const float scale = 0.12751742522f;   // (1/sqrt(128)) * log2(e)

    int idx = blockIdx.x * blockDim.x + threadIdx.x;
    if (idx < QTOT) {
        int i = idx & 63;
        int h = (idx >> 6) & 15;
        int t = idx >> 10;
        int s = t & (SEQ - 1), b = t >> 11;
        const __half* src = g_qkv16 + (size_t)t * QKVN + h * HDIM + i;
        float x1 = __half2float(src[0]);
        float x2 = __half2float(src[64]);
        float2 cssn = g_rope_tab[s * 64 + i];
        size_t dst = ((size_t)(b * NHEADS + h) * SEQ + s) * HDIM + i;
        g_qh[dst]      = __float2half_rn((x1 * cssn.x - x2 * cssn.y) * scale);
        g_qh[dst + 64] = __float2half_rn((x2 * cssn.x + x1 * cssn.y) * scale);
    } else if (idx < QTOT + KTOT) {
        int j = idx - QTOT;
        int i = j & 63;
        int kvh = (j >> 6) & 3;
        int t = j >> 8;
        int s = t & (SEQ - 1), b = t >> 11;
        const __half* src = g_qkv16 + (size_t)t * QKVN + EMBED + kvh * HDIM + i;
        float x1 = __half2float(src[0]);
        float x2 = __half2float(src[64]);
        float2 cssn = g_rope_tab[s * 64 + i];
        size_t dst = ((size_t)(b * NKV + kvh) * SEQ + s) * HDIM + i;
        g_kh[dst]      = __float2half_rn(x1 * cssn.x - x2 * cssn.y);
        g_kh[dst + 64] = __float2half_rn(x2 * cssn.x + x1 * cssn.y);
    } else if (idx < QTOT + KTOT + VTOT) {
        int j = idx - QTOT - KTOT;
        int d2 = j & 63;
        int rest = j >> 6;
        int kvh = rest & 3;
        int t = rest >> 2;
        int s = t & (SEQ - 1), b = t >> 11;
        const __half2* src = (const __half2*)(g_qkv16 + (size_t)t * QKVN + EMBED + 512 + kvh * HDIM);
        __half2* dst = (__half2*)(g_vh + ((size_t)(b * NKV + kvh) * SEQ + s) * HDIM);
        dst[d2] = src[d2];
    }
}

// ---------------------------------------------------------------------------
// Flash attention fp16 (unchanged from R15): 128 q-rows/CTA, 4 warps x 32
// q-rows, base-2 softmax with ex2.approx.f16x2, l via constant ones-fragment
// mma, 2-stage K/V cp.async, 128 threads, 2 CTAs/SM (smem 104448 B).
// ---------------------------------------------------------------------------
#define AT_QS 0
#define AT_KS 34816
#define AT_VS 69632
#define AT_SMEM 104448

__global__ __launch_bounds__(128, 2) void attn_h()
{
    extern __shared__ char smc[];
    const uint32_t sb = smem_to_u32(smc);

    const int q0   = blockIdx.x * 128;
    const int h    = blockIdx.y;
    const int b    = blockIdx.z;
    const int kvh  = h >> 2;
    const int tid  = threadIdx.x;     // 0..127
    const int lane = tid & 31;
    const int w    = tid >> 5;        // 0..3, rows [w*32, w*32+32)
    const int lr   = lane >> 2;
    const int lc   = lane & 3;

    const __half* qsrc = g_qh + ((size_t)(b * NHEADS + h) * SEQ + q0) * HDIM;
    const __half* ksrc = g_kh + (size_t)(b * NKV + kvh) * SEQ * HDIM;
    const __half* vsrc = g_vh + (size_t)(b * NKV + kvh) * SEQ * HDIM;

    // Constant ones B-fragment: B[k][n] = (n==0). Lanes 0-3 => n==0.
    const uint32_t bl_ones = (lane < 4) ? 0x3C003C00u : 0u;
    const uint32_t blf[2] = { bl_ones, bl_ones };

    auto issue_kv = [&](int kt) {
        const int buf = kt & 1;
        const int kv0 = kt * 64;
#pragma unroll
        for (int i = 0; i < 8; i++) {
            int slot = tid + i * 128;
            int r = slot >> 4, c = slot & 15;
            cp16(sb + AT_KS + buf * 17408 + r * 272 + c * 16,
                 ksrc + (size_t)(kv0 + r) * HDIM + c * 8);
            cp16(sb + AT_VS + buf * 17408 + r * 272 + c * 16,
                 vsrc + (size_t)(kv0 + r) * HDIM + c * 8);
        }
        CP_COMMIT();
    };

    // Prologue: Q + KV tile 0 in one group
#pragma unroll
    for (int i = 0; i < 16; i++) {
        int slot = tid + i * 128;
        int r = slot >> 4, c = slot & 15;
        cp16(sb + AT_QS + r * 272 + c * 16, qsrc + (size_t)r * HDIM + c * 8);
    }
#pragma unroll
    for (int i = 0; i < 8; i++) {
        int slot = tid + i * 128;
        int r = slot >> 4, c = slot & 15;
        cp16(sb + AT_KS + r * 272 + c * 16, ksrc + (size_t)r * HDIM + c * 8);
        cp16(sb + AT_VS + r * 272 + c * 16, vsrc + (size_t)r * HDIM + c * 8);
    }
    CP_COMMIT();

    // ldmatrix lane bases
    const uint32_t q_base = sb + AT_QS + (w * 32 + (lane & 15)) * 272 + (lane >> 4) * 16;
    const uint32_t k_base = sb + AT_KS
        + (((lane >> 4) << 3) + (lane & 7)) * 272 + ((lane >> 3) & 1) * 16;
    const uint32_t v_base = sb + AT_VS + (lane & 15) * 272 + (lane >> 4) * 16;

    // Softmax max state per (mi, row-half), in base-2 units
    float m00 = -INFINITY, m01 = -INFINITY, m10 = -INFINITY, m11 = -INFINITY;

    float o_acc[2][16][4];
    float o_l[2][4];                    // l accumulator (ones-fragment mma)
#pragma unroll
    for (int mi = 0; mi < 2; mi++) {
#pragma unroll
        for (int ni = 0; ni < 16; ni++)
#pragma unroll
            for (int c = 0; c < 4; c++) o_acc[mi][ni][c] = 0.f;
#pragma unroll
        for (int c = 0; c < 4; c++) o_l[mi][c] = 0.f;
    }

    const int NT = SEQ / 64;   // 32
    for (int kt = 0; kt < NT; kt++) {
        CP_WAIT0();
        __syncthreads();                   // buf kt ready; all warps past kt-1
        if (kt + 1 < NT) issue_kv(kt + 1);

        const uint32_t kb = (kt & 1) * 17408;

        // S = Q @ K^T : warp rows [w*32,+32) x all 64 kv cols (base-2 units)
        float sfr[2][8][4];
#pragma unroll
        for (int mi = 0; mi < 2; mi++)
#pragma unroll
            for (int ni = 0; ni < 8; ni++)
#pragma unroll
                for (int c = 0; c < 4; c++) sfr[mi][ni][c] = 0.f;

#pragma unroll
        for (int ks = 0; ks < 8; ks++) {
            uint32_t af0[4], af1[4];
            ldsm4(af0, q_base + ks * 32);
            ldsm4(af1, q_base + 4352 + ks * 32);   // +16 rows
#pragma unroll
            for (int np = 0; np < 4; np++) {
                uint32_t bf[4];
                ldsm4(bf, k_base + kb + np * 4352 + ks * 32);
                mma16(sfr[0][np * 2],     af0, bf);
                mma16(sfr[0][np * 2 + 1], af0, bf + 2);
                mma16(sfr[1][np * 2],     af1, bf);
                mma16(sfr[1][np * 2 + 1], af1, bf + 2);
            }
        }

        // Warp-local online softmax (base-2): max + ex2.f16x2, pack in-place
        float corr00, corr01, corr10, corr11;
#pragma unroll
        for (int mi = 0; mi < 2; mi++) {
            float mx0 = -INFINITY, mx1 = -INFINITY;
#pragma unroll
            for (int ni = 0; ni < 8; ni++) {
                mx0 = fmaxf(mx0, fmaxf(sfr[mi][ni][0], sfr[mi][ni][1]));
                mx1 = fmaxf(mx1, fmaxf(sfr[mi][ni][2], sfr[mi][ni][3]));
            }
            mx0 = fmaxf(mx0, __shfl_xor_sync(0xffffffffu, mx0, 1));
            mx0 = fmaxf(mx0, __shfl_xor_sync(0xffffffffu, mx0, 2));
            mx1 = fmaxf(mx1, __shfl_xor_sync(0xffffffffu, mx1, 1));
            mx1 = fmaxf(mx1, __shfl_xor_sync(0xffffffffu, mx1, 2));

            float mold0 = mi ? m10 : m00;
            float mold1 = mi ? m11 : m01;
            float mn0 = fmaxf(mold0, mx0);
            float mn1 = fmaxf(mold1, mx1);
            float c0 = ex2f(mold0 - mn0);
            float c1 = ex2f(mold1 - mn1);

#pragma unroll
            for (int ni = 0; ni < 8; ni++) {
                uint32_t* sp = (uint32_t*)&sfr[mi][ni][0];
                sp[0] = h2exp2u(pack_h2(sfr[mi][ni][0] - mn0, sfr[mi][ni][1] - mn0));
                sp[1] = h2exp2u(pack_h2(sfr[mi][ni][2] - mn1, sfr[mi][ni][3] - mn1));
            }

            if (mi == 0) { m00 = mn0; m01 = mn1; corr00 = c0; corr01 = c1; }
            else         { m10 = mn0; m11 = mn1; corr10 = c0; corr11 = c1; }
        }

        // Rescale O (and l) accumulators
#pragma unroll
        for (int ni = 0; ni < 16; ni++) {
            o_acc[0][ni][0] *= corr00; o_acc[0][ni][1] *= corr00;
            o_acc[0][ni][2] *= corr01; o_acc[0][ni][3] *= corr01;
            o_acc[1][ni][0] *= corr10; o_acc[1][ni][1] *= corr10;
            o_acc[1][ni][2] *= corr11; o_acc[1][ni][3] *= corr11;
        }
        o_l[0][0] *= corr00; o_l[0][1] *= corr00; o_l[0][2] *= corr01; o_l[0][3] *= corr01;
        o_l[1][0] *= corr10; o_l[1][1] *= corr10; o_l[1][2] *= corr11; o_l[1][3] *= corr11;

        // O += P @ V ; l += P @ ones (constant fragment, no memory traffic)
#pragma unroll
        for (int kk = 0; kk < 4; kk++) {
            uint32_t pa0[4] = { *(uint32_t*)&sfr[0][kk*2][0], *(uint32_t*)&sfr[0][kk*2][1],
                                *(uint32_t*)&sfr[0][kk*2+1][0], *(uint32_t*)&sfr[0][kk*2+1][1] };
            uint32_t pa1[4] = { *(uint32_t*)&sfr[1][kk*2][0], *(uint32_t*)&sfr[1][kk*2][1],
                                *(uint32_t*)&sfr[1][kk*2+1][0], *(uint32_t*)&sfr[1][kk*2+1][1] };
#pragma unroll
            for (int np = 0; np < 8; np++) {
                uint32_t bf[4];
                ldsm4t(bf, v_base + kb + kk * 4352 + np * 32);
                mma16(o_acc[0][np * 2],     pa0, bf);
                mma16(o_acc[0][np * 2 + 1], pa0, bf + 2);
                mma16(o_acc[1][np * 2],     pa1, bf);
                mma16(o_acc[1][np * 2 + 1], pa1, bf + 2);
            }
            mma16(o_l[0], pa0, blf);
            mma16(o_l[1], pa1, blf);
        }
    }

    // l lives in col 0 -> quad-lane lc==0, c0 (row lr) / c2 (row lr+8).
#pragma unroll
    for (int mi = 0; mi < 2; mi++) {
        float lv0 = __shfl_sync(0xffffffffu, o_l[mi][0], lane & ~3);
        float lv1 = __shfl_sync(0xffffffffu, o_l[mi][2], lane & ~3);
        float i0 = 1.0f / lv0;
        float i1 = 1.0f / lv1;
        int row = b * SEQ + q0 + w * 32 + mi * 16 + lr;
#pragma unroll
        for (int ni = 0; ni < 16; ni++) {
            int d = ni * 8 + 2 * lc;
            __half2 h0 = __floats2half2_rn(o_acc[mi][ni][0] * i0, o_acc[mi][ni][1] * i0);
            __half2 h1 = __floats2half2_rn(o_acc[mi][ni][2] * i1, o_acc[mi][ni][3] * i1);
            *(__half2*)(g_oh + (size_t)row * EMBED + h * HDIM + d)       = h0;
            *(__half2*)(g_oh + (size_t)(row + 8) * EMBED + h * HDIM + d) = h1;
        }
    }
}

// ---------------------------------------------------------------------------
extern "C" void kernel_launch(void* const* d_in, const int* in_sizes, int n_in,
                              void* d_out, int out_size)
{
    const float* x   = (const float*)d_in[0];
    const float* Wq  = (const float*)d_in[1];
    const float* bq  = (const float*)d_in[2];
    const float* Wkv = (const float*)d_in[3];
    const float* bkv = (const float*)d_in[4];
    const float* Wo  = (const float*)d_in[5];
    float* out = (float*)d_out;

    __half *xh, *wh, *woh, *qkv16, *oh;
    float* bqkv;
    cudaGetSymbolAddress((void**)&xh,    g_xh);
    cudaGetSymbolAddress((void**)&wh,    g_wh);
    cudaGetSymbolAddress((void**)&woh,   g_woh);
    cudaGetSymbolAddress((void**)&qkv16, g_qkv16);
    cudaGetSymbolAddress((void**)&oh,    g_oh);
    cudaGetSymbolAddress((void**)&bqkv,  g_bqkv);

    const int GEMM_SMEM = 221184;   // 4 stages x 55296
    cudaFuncSetAttribute(gemm_h<true>,  cudaFuncAttributeMaxDynamicSharedMemorySize, GEMM_SMEM);
    cudaFuncSetAttribute(gemm_h<false>, cudaFuncAttributeMaxDynamicSharedMemorySize, GEMM_SMEM);
    cudaFuncSetAttribute(attn_h, cudaFuncAttributeMaxDynamicSharedMemorySize, AT_SMEM);

    // 0) conversions + rope table + stacked bias (single launch)
    {
        int total = (NTOK * EMBED + 2 * EMBED * EMBED + KVDIM * EMBED) / 4
                  + SEQ * 64 + QKVN;
        prep_all<<<(total + 255) / 256, 256>>>((const float4*)x, (const float4*)Wq,
                                               (const float4*)Wkv, (const float4*)Wo,
                                               bq, bkv);
    }
    // 1) fused qkv = x @ [Wq;Wkv]^T + [bq;bkv]  (fp16 out, CTA 256x128)
    gemm_h<true><<<dim3(QKVN/128, NTOK/256), 256, GEMM_SMEM>>>(xh, wh, bqkv, qkv16, NTOK, QKVN, EMBED);
    // 2) RoPE + repack (Q pre-scaled for base-2 softmax)
    {
        int total = NTOK*NHEADS*64 + NTOK*NKV*64 + NTOK*NKV*64;
        rope_h<<<(total + 255) / 256, 256>>>();
    }
    // 3) flash attention -> g_oh  (128 threads, 2 CTAs/SM)
    attn_h<<<dim3(SEQ/128, NHEADS, BATCH), 128, AT_SMEM>>>();
    // 4) out = o @ Wo^T  (fp32 out, CTA 256x128)
    gemm_h<false><<<dim3(EMBED/128, NTOK/256), 256, GEMM_SMEM>>>(oh, woh, nullptr, out, NTOK, EMBED, EMBED);
}

// round 17
// speedup vs baseline: 1.0397x; 1.0397x over previous
#include <cuda_runtime.h>
#include <cuda_fp16.h>
#include <math.h>
#include <stdint.h>

#define EMBED   2048
#define NHEADS  16
#define NKV     4
#define HDIM    128
#define BATCH   2
#define SEQ     2048
#define NTOK    (BATCH*SEQ)      // 4096
#define KVDIM   1024             // k(512) + v(512)
#define QKVN    (EMBED + KVDIM)  // 3072 fused projection width

// fp16 scratch
__device__ __half g_xh [NTOK * EMBED];
__device__ __half g_wh [QKVN * EMBED];     // Wq rows 0..2047, Wkv rows 2048..3071
__device__ __half g_woh[EMBED * EMBED];
__device__ __half g_qh [NTOK * EMBED];     // [b][h][s][d], rope'd + scaled*log2e
__device__ __half g_kh [NTOK * 512];       // [b][kvh][s][d], rope'd
__device__ __half g_vh [NTOK * 512];       // [b][kvh][s][d]
__device__ __half g_oh [NTOK * EMBED];     // attention out (token-major)
// aux
__device__ float2 g_rope_tab[SEQ * 64];    // (cos, sin) per (s, i)
__device__ float  g_bqkv[QKVN];            // stacked bias

// ---------------------------------------------------------------------------
// PTX helpers (baseline sm_80+ features only)
// ---------------------------------------------------------------------------
__device__ __forceinline__ uint32_t smem_to_u32(const void* p) {
    uint32_t a;
    asm("{ .reg .u64 t; cvta.to.shared.u64 t, %1; cvt.u32.u64 %0, t; }" : "=r"(a) : "l"(p));
    return a;
}

__device__ __forceinline__ void mma16(float c[4], const uint32_t a[4], const uint32_t b[2]) {
    asm volatile(
        "mma.sync.aligned.m16n8k16.row.col.f32.f16.f16.f32 "
        "{%0,%1,%2,%3},{%4,%5,%6,%7},{%8,%9},{%0,%1,%2,%3};"
        : "+f"(c[0]), "+f"(c[1]), "+f"(c[2]), "+f"(c[3])
        : "r"(a[0]), "r"(a[1]), "r"(a[2]), "r"(a[3]), "r"(b[0]), "r"(b[1]));
}

__device__ __forceinline__ void ldsm4(uint32_t r[4], uint32_t addr) {
    asm volatile("ldmatrix.sync.aligned.m8n8.x4.shared.b16 {%0,%1,%2,%3}, [%4];"
        : "=r"(r[0]), "=r"(r[1]), "=r"(r[2]), "=r"(r[3]) : "r"(addr));
}

__device__ __forceinline__ void ldsm4t(uint32_t r[4], uint32_t addr) {
    asm volatile("ldmatrix.sync.aligned.m8n8.x4.trans.shared.b16 {%0,%1,%2,%3}, [%4];"
        : "=r"(r[0]), "=r"(r[1]), "=r"(r[2]), "=r"(r[3]) : "r"(addr));
}

__device__ __forceinline__ void cp16(uint32_t dst, const void* src) {
    asm volatile("cp.async.cg.shared.global [%0], [%1], 16;" :: "r"(dst), "l"(src));
}
#define CP_COMMIT() asm volatile("cp.async.commit_group;" ::: "memory")
#define CP_WAIT0()  asm volatile("cp.async.wait_group 0;" ::: "memory")
#define CP_WAIT1()  asm volatile("cp.async.wait_group 1;" ::: "memory")

__device__ __forceinline__ float ex2f(float x) {
    float r; asm("ex2.approx.f32 %0, %1;" : "=f"(r) : "f"(x)); return r;
}
__device__ __forceinline__ uint32_t h2exp2u(uint32_t x) {
    uint32_t r; asm("ex2.approx.f16x2 %0, %1;" : "=r"(r) : "r"(x)); return r;
}
__device__ __forceinline__ uint32_t pack_h2(float a, float b) {
    __half2 h = __floats2half2_rn(a, b);
    return *(uint32_t*)&h;
}

// ---------------------------------------------------------------------------
// Fused prep: fp32->fp16 of x, Wq|Wkv (packed), Wo; RoPE table; stacked bias.
// ---------------------------------------------------------------------------
__global__ void prep_all(const float4* __restrict__ x,  const float4* __restrict__ wq,
                         const float4* __restrict__ wkv, const float4* __restrict__ wo,
                         const float* __restrict__ bq,  const float* __restrict__ bkv)
{
    const int n_x   = NTOK * EMBED / 4;
    const int n_wq  = EMBED * EMBED / 4;
    const int n_wkv = KVDIM * EMBED / 4;
    const int n_wo  = EMBED * EMBED / 4;
    const int n_tab = SEQ * 64;
    int i = blockIdx.x * blockDim.x + threadIdx.x;

    int base = 0;
    if (i < (base += n_x)) {
        int j = i;
        float4 v = x[j];
        __half2 h0 = __floats2half2_rn(v.x, v.y), h1 = __floats2half2_rn(v.z, v.w);
        ((uint2*)g_xh)[j] = make_uint2(*(uint32_t*)&h0, *(uint32_t*)&h1);
    } else if (i < (base += n_wq)) {
        int j = i - (base - n_wq);
        float4 v = wq[j];
        __half2 h0 = __floats2half2_rn(v.x, v.y), h1 = __floats2half2_rn(v.z, v.w);
        ((uint2*)g_wh)[j] = make_uint2(*(uint32_t*)&h0, *(uint32_t*)&h1);
    } else if (i < (base += n_wkv)) {
        int j = i - (base - n_wkv);
        float4 v = wkv[j];
        __half2 h0 = __floats2half2_rn(v.x, v.y), h1 = __floats2half2_rn(v.z, v.w);
        ((uint2*)(g_wh + (size_t)EMBED * EMBED))[j] = make_uint2(*(uint32_t*)&h0, *(uint32_t*)&h1);
    } else if (i < (base += n_wo)) {
        int j = i - (base - n_wo);
        float4 v = wo[j];
        __half2 h0 = __floats2half2_rn(v.x, v.y), h1 = __floats2half2_rn(v.z, v.w);
        ((uint2*)g_woh)[j] = make_uint2(*(uint32_t*)&h0, *(uint32_t*)&h1);
    } else if (i < (base += n_tab)) {
        int j = i - (base - n_tab);
        int s = j >> 6, d = j & 63;
        float freq = powf(10000.0f, -(float)d * (1.0f / 64.0f));
        float sn, cs; sincosf((float)s * freq, &sn, &cs);
        g_rope_tab[j] = make_float2(cs, sn);
    } else if (i < (base += QKVN)) {
        int j = i - (base - QKVN);
        g_bqkv[j] = (j < EMBED) ? bq[j] : bkv[j - EMBED];
    }
}

// ---------------------------------------------------------------------------
// GEMM (R15-proven config): CTA 128x128, BK=64, 8 warps (32x64), 3-stage
// cp.async, single sync per k-tile, 2 CTAs/SM.
// MODE 0: C = A@W^T + bias, fp32 out (Wo projection).
// MODE 1: fused QKV epilogue — CTA col-tile == one head (blockIdx.x = head
//   slot 0..23). Stage fp32 C(+bias) in smem, then apply table-RoPE pairs
//   (i, i+64) and write g_qh (scaled*log2e) / g_kh / g_vh directly.
// ---------------------------------------------------------------------------
#define CS_LD 136   // fp32 C-tile stride (floats) for epilogue staging

template <int MODE>
__global__ __launch_bounds__(256, 2) void gemm_h(
    const __half* __restrict__ A, const __half* __restrict__ W,
    const float* __restrict__ bias, float* __restrict__ Cout,
    int M, int N, int K)
{
    extern __shared__ char smc[];
    const uint32_t sb = smem_to_u32(smc);

    const int bm   = blockIdx.y * 128;
    const int bn   = blockIdx.x * 128;
    const int tid  = threadIdx.x;
    const int lane = tid & 31;
    const int w    = tid >> 5;
    const int mw   = w & 3;
    const int nw   = w >> 2;
    const int lr   = lane >> 2;
    const int lc   = lane & 3;

    float acc[2][8][4];
#pragma unroll
    for (int mi = 0; mi < 2; mi++)
#pragma unroll
        for (int ni = 0; ni < 8; ni++)
#pragma unroll
            for (int c = 0; c < 4; c++) acc[mi][ni][c] = 0.f;

    const int NT = K / 64;

    auto issue = [&](int t) {
        const int buf = t % 3;
        const int kb  = t * 64;
        uint32_t abuf = sb + buf * 36864;
        uint32_t bbuf = abuf + 18432;
#pragma unroll
        for (int i = 0; i < 4; i++) {
            int slot = tid + i * 256;
            int r = slot >> 3, c = slot & 7;
            cp16(abuf + r * 144 + c * 16, A + (size_t)(bm + r) * K + kb + c * 8);
            cp16(bbuf + r * 144 + c * 16, W + (size_t)(bn + r) * K + kb + c * 8);
        }
        CP_COMMIT();
    };

    const uint32_t a_base = sb + (mw * 32 + (lane & 15)) * 144 + (lane >> 4) * 16;
    const uint32_t b_base = sb + 18432
        + (nw * 64 + ((lane >> 4) << 3) + (lane & 7)) * 144 + ((lane >> 3) & 1) * 16;

    issue(0);
    issue(1);

    for (int t = 0; t < NT; t++) {
        if (t + 1 < NT) { CP_WAIT1(); } else { CP_WAIT0(); }
        __syncthreads();               // buf t ready; all warps past compute(t-1)
        if (t + 2 < NT) issue(t + 2);  // overwrites buf (t-1)%3 — safe post-sync

        const uint32_t boff = (t % 3) * 36864;
#pragma unroll
        for (int ks = 0; ks < 4; ks++) {
            uint32_t af0[4], af1[4];
            ldsm4(af0, a_base + boff + ks * 32);
            ldsm4(af1, a_base + boff + 2304 + ks * 32);
#pragma unroll
            for (int np = 0; np < 4; np++) {
                uint32_t bf[4];
                ldsm4(bf, b_base + boff + np * 2304 + ks * 32);
                mma16(acc[0][np * 2],     af0, bf);
                mma16(acc[0][np * 2 + 1], af0, bf + 2);
                mma16(acc[1][np * 2],     af1, bf);
                mma16(acc[1][np * 2 + 1], af1, bf + 2);
            }
        }
    }

    if (MODE == 0) {
        // fp32 epilogue (no bias in this path's use, but keep generic)
#pragma unroll
        for (int mi = 0; mi < 2; mi++) {
            int r = bm + mw * 32 + mi * 16 + lr;
#pragma unroll
            for (int ni = 0; ni < 8; ni++) {
                int cc = bn + nw * 64 + ni * 8 + 2 * lc;
                float b0 = bias ? bias[cc] : 0.f;
                float b1 = bias ? bias[cc + 1] : 0.f;
                *(float2*)(Cout + (size_t)r * N + cc) =
                    make_float2(acc[mi][ni][0] + b0, acc[mi][ni][1] + b1);
                *(float2*)(Cout + (size_t)(r + 8) * N + cc) =
                    make_float2(acc[mi][ni][2] + b0, acc[mi][ni][3] + b1);
            }
        }
    } else {
        // Fused QKV epilogue: stage C(+bias) fp32 in smem, rope, write halves.
        __syncthreads();   // all warps done reading stage buffers
        float* Cs = (float*)smc;   // [128][CS_LD]
#pragma unroll
        for (int mi = 0; mi < 2; mi++) {
            int rl = mw * 32 + mi * 16 + lr;
#pragma unroll
            for (int ni = 0; ni < 8; ni++) {
                int cl = nw * 64 + ni * 8 + 2 * lc;
                float b0 = g_bqkv[bn + cl];
                float b1 = g_bqkv[bn + cl + 1];
                *(float2*)&Cs[rl * CS_LD + cl] =
                    make_float2(acc[mi][ni][0] + b0, acc[mi][ni][1] + b1);
                *(float2*)&Cs[(rl + 8) * CS_LD + cl] =
                    make_float2(acc[mi][ni][2] + b0, acc[mi][ni][3] + b1);
            }
        }
        __syncthreads();

        const int hh = blockIdx.x;          // head slot: q 0..15, k 16..19, v 20..23
        const float qscale = 0.12751742522f;  // (1/sqrt(128)) * log2(e)
#pragma unroll
        for (int it = 0; it < 32; it++) {
            int idx = tid + it * 256;       // 0..8191
            int row = idx >> 6, i = idx & 63;
            int tok = bm + row;
            int s = tok & (SEQ - 1), b = tok >> 11;
            float c1 = Cs[row * CS_LD + i];
            float c2 = Cs[row * CS_LD + i + 64];
            if (hh < 16) {
                float2 t = g_rope_tab[s * 64 + i];
                size_t base = ((size_t)(b * NHEADS + hh) * SEQ + s) * HDIM + i;
                g_qh[base]      = __float2half_rn((c1 * t.x - c2 * t.y) * qscale);
                g_qh[base + 64] = __float2half_rn((c2 * t.x + c1 * t.y) * qscale);
            } else if (hh < 20) {
                float2 t = g_rope_tab[s * 64 + i];
                size_t base = ((size_t)(b * NKV + (hh - 16)) * SEQ + s) * HDIM + i;
                g_kh[base]      = __float2half_rn(c1 * t.x - c2 * t.y);
                g_kh[base + 64] = __float2half_rn(c2 * t.x + c1 * t.y);
            } else {
                size_t base = ((size_t)(b * NKV + (hh - 20)) * SEQ + s) * HDIM + i;
                g_vh[base]      = __float2half_rn(c1);
                g_vh[base + 64] = __float2half_rn(c2);
            }
        }
    }
}

// ---------------------------------------------------------------------------
// Flash attention fp16 (unchanged from R15): 128 q-rows/CTA, 4 warps x 32
// q-rows, base-2 softmax with ex2.approx.f16x2, l via constant ones-fragment
// mma, 2-stage K/V cp.async, 128 threads, 2 CTAs/SM (smem 104448 B).
// ---------------------------------------------------------------------------
#define AT_QS 0
#define AT_KS 34816
#define AT_VS 69632
#define AT_SMEM 104448

__global__ __launch_bounds__(128, 2) void attn_h()
{
    extern __shared__ char smc[];
    const uint32_t sb = smem_to_u32(smc);

    const int q0   = blockIdx.x * 128;
    const int h    = blockIdx.y;
    const int b    = blockIdx.z;
    const int kvh  = h >> 2;
    const int tid  = threadIdx.x;     // 0..127
    const int lane = tid & 31;
    const int w    = tid >> 5;        // 0..3, rows [w*32, w*32+32)
    const int lr   = lane >> 2;
    const int lc   = lane & 3;

    const __half* qsrc = g_qh + ((size_t)(b * NHEADS + h) * SEQ + q0) * HDIM;
    const __half* ksrc = g_kh + (size_t)(b * NKV + kvh) * SEQ * HDIM;
    const __half* vsrc = g_vh + (size_t)(b * NKV + kvh) * SEQ * HDIM;

    // Constant ones B-fragment: B[k][n] = (n==0). Lanes 0-3 => n==0.
    const uint32_t bl_ones = (lane < 4) ? 0x3C003C00u : 0u;
    const uint32_t blf[2] = { bl_ones, bl_ones };

    auto issue_kv = [&](int kt) {
        const int buf = kt & 1;
        const int kv0 = kt * 64;
#pragma unroll
        for (int i = 0; i < 8; i++) {
            int slot = tid + i * 128;
            int r = slot >> 4, c = slot & 15;
            cp16(sb + AT_KS + buf * 17408 + r * 272 + c * 16,
                 ksrc + (size_t)(kv0 + r) * HDIM + c * 8);
            cp16(sb + AT_VS + buf * 17408 + r * 272 + c * 16,
                 vsrc + (size_t)(kv0 + r) * HDIM + c * 8);
        }
        CP_COMMIT();
    };

    // Prologue: Q + KV tile 0 in one group
#pragma unroll
    for (int i = 0; i < 16; i++) {
        int slot = tid + i * 128;
        int r = slot >> 4, c = slot & 15;
        cp16(sb + AT_QS + r * 272 + c * 16, qsrc + (size_t)r * HDIM + c * 8);
    }
#pragma unroll
    for (int i = 0; i < 8; i++) {
        int slot = tid + i * 128;
        int r = slot >> 4, c = slot & 15;
        cp16(sb + AT_KS + r * 272 + c * 16, ksrc + (size_t)r * HDIM + c * 8);
        cp16(sb + AT_VS + r * 272 + c * 16, vsrc + (size_t)r * HDIM + c * 8);
    }
    CP_COMMIT();

    // ldmatrix lane bases
    const uint32_t q_base = sb + AT_QS + (w * 32 + (lane & 15)) * 272 + (lane >> 4) * 16;
    const uint32_t k_base = sb + AT_KS
        + (((lane >> 4) << 3) + (lane & 7)) * 272 + ((lane >> 3) & 1) * 16;
    const uint32_t v_base = sb + AT_VS + (lane & 15) * 272 + (lane >> 4) * 16;

    // Softmax max state per (mi, row-half), in base-2 units
    float m00 = -INFINITY, m01 = -INFINITY, m10 = -INFINITY, m11 = -INFINITY;

    float o_acc[2][16][4];
    float o_l[2][4];                    // l accumulator (ones-fragment mma)
#pragma unroll
    for (int mi = 0; mi < 2; mi++) {
#pragma unroll
        for (int ni = 0; ni < 16; ni++)
#pragma unroll
            for (int c = 0; c < 4; c++) o_acc[mi][ni][c] = 0.f;
#pragma unroll
        for (int c = 0; c < 4; c++) o_l[mi][c] = 0.f;
    }

    const int NT = SEQ / 64;   // 32
    for (int kt = 0; kt < NT; kt++) {
        CP_WAIT0();
        __syncthreads();                   // buf kt ready; all warps past kt-1
        if (kt + 1 < NT) issue_kv(kt + 1);

        const uint32_t kb = (kt & 1) * 17408;

        // S = Q @ K^T : warp rows [w*32,+32) x all 64 kv cols (base-2 units)
        float sfr[2][8][4];
#pragma unroll
        for (int mi = 0; mi < 2; mi++)
#pragma unroll
            for (int ni = 0; ni < 8; ni++)
#pragma unroll
                for (int c = 0; c < 4; c++) sfr[mi][ni][c] = 0.f;

#pragma unroll
        for (int ks = 0; ks < 8; ks++) {
            uint32_t af0[4], af1[4];
            ldsm4(af0, q_base + ks * 32);
            ldsm4(af1, q_base + 4352 + ks * 32);   // +16 rows
#pragma unroll
            for (int np = 0; np < 4; np++) {
                uint32_t bf[4];
                ldsm4(bf, k_base + kb + np * 4352 + ks * 32);
                mma16(sfr[0][np * 2],     af0, bf);
                mma16(sfr[0][np * 2 + 1], af0, bf + 2);
                mma16(sfr[1][np * 2],     af1, bf);
                mma16(sfr[1][np * 2 + 1], af1, bf + 2);
            }
        }

        // Warp-local online softmax (base-2): max + ex2.f16x2, pack in-place
        float corr00, corr01, corr10, corr11;
#pragma unroll
        for (int mi = 0; mi < 2; mi++) {
            float mx0 = -INFINITY, mx1 = -INFINITY;
#pragma unroll
            for (int ni = 0; ni < 8; ni++) {
                mx0 = fmaxf(mx0, fmaxf(sfr[mi][ni][0], sfr[mi][ni][1]));
                mx1 = fmaxf(mx1, fmaxf(sfr[mi][ni][2], sfr[mi][ni][3]));
            }
            mx0 = fmaxf(mx0, __shfl_xor_sync(0xffffffffu, mx0, 1));
            mx0 = fmaxf(mx0, __shfl_xor_sync(0xffffffffu, mx0, 2));
            mx1 = fmaxf(mx1, __shfl_xor_sync(0xffffffffu, mx1, 1));
            mx1 = fmaxf(mx1, __shfl_xor_sync(0xffffffffu, mx1, 2));

            float mold0 = mi ? m10 : m00;
            float mold1 = mi ? m11 : m01;
            float mn0 = fmaxf(mold0, mx0);
            float mn1 = fmaxf(mold1, mx1);
            float c0 = ex2f(mold0 - mn0);
            float c1 = ex2f(mold1 - mn1);

#pragma unroll
            for (int ni = 0; ni < 8; ni++) {
                uint32_t* sp = (uint32_t*)&sfr[mi][ni][0];
                sp[0] = h2exp2u(pack_h2(sfr[mi][ni][0] - mn0, sfr[mi][ni][1] - mn0));
                sp[1] = h2exp2u(pack_h2(sfr[mi][ni][2] - mn1, sfr[mi][ni][3] - mn1));
            }

            if (mi == 0) { m00 = mn0; m01 = mn1; corr00 = c0; corr01 = c1; }
            else         { m10 = mn0; m11 = mn1; corr10 = c0; corr11 = c1; }
        }

        // Rescale O (and l) accumulators
#pragma unroll
        for (int ni = 0; ni < 16; ni++) {
            o_acc[0][ni][0] *= corr00; o_acc[0][ni][1] *= corr00;
            o_acc[0][ni][2] *= corr01; o_acc[0][ni][3] *= corr01;
            o_acc[1][ni][0] *= corr10; o_acc[1][ni][1] *= corr10;
            o_acc[1][ni][2] *= corr11; o_acc[1][ni][3] *= corr11;
        }
        o_l[0][0] *= corr00; o_l[0][1] *= corr00; o_l[0][2] *= corr01; o_l[0][3] *= corr01;
        o_l[1][0] *= corr10; o_l[1][1] *= corr10; o_l[1][2] *= corr11; o_l[1][3] *= corr11;

        // O += P @ V ; l += P @ ones (constant fragment, no memory traffic)
#pragma unroll
        for (int kk = 0; kk < 4; kk++) {
            uint32_t pa0[4] = { *(uint32_t*)&sfr[0][kk*2][0], *(uint32_t*)&sfr[0][kk*2][1],
                                *(uint32_t*)&sfr[0][kk*2+1][0], *(uint32_t*)&sfr[0][kk*2+1][1] };
            uint32_t pa1[4] = { *(uint32_t*)&sfr[1][kk*2][0], *(uint32_t*)&sfr[1][kk*2][1],
                                *(uint32_t*)&sfr[1][kk*2+1][0], *(uint32_t*)&sfr[1][kk*2+1][1] };
#pragma unroll
            for (int np = 0; np < 8; np++) {
                uint32_t bf[4];
                ldsm4t(bf, v_base + kb + kk * 4352 + np * 32);
                mma16(o_acc[0][np * 2],     pa0, bf);
                mma16(o_acc[0][np * 2 + 1], pa0, bf + 2);
                mma16(o_acc[1][np * 2],     pa1, bf);
                mma16(o_acc[1][np * 2 + 1], pa1, bf + 2);
            }
            mma16(o_l[0], pa0, blf);
            mma16(o_l[1], pa1, blf);
        }
    }

    // l lives in col 0 -> quad-lane lc==0, c0 (row lr) / c2 (row lr+8).
#pragma unroll
    for (int mi = 0; mi < 2; mi++) {
        float lv0 = __shfl_sync(0xffffffffu, o_l[mi][0], lane & ~3);
        float lv1 = __shfl_sync(0xffffffffu, o_l[mi][2], lane & ~3);
        float i0 = 1.0f / lv0;
        float i1 = 1.0f / lv1;
        int row = b * SEQ + q0 + w * 32 + mi * 16 + lr;
#pragma unroll
        for (int ni = 0; ni < 16; ni++) {
            int d = ni * 8 + 2 * lc;
            __half2 h0 = __floats2half2_rn(o_acc[mi][ni][0] * i0, o_acc[mi][ni][1] * i0);
            __half2 h1 = __floats2half2_rn(o_acc[mi][ni][2] * i1, o_acc[mi][ni][3] * i1);
            *(__half2*)(g_oh + (size_t)row * EMBED + h * HDIM + d)       = h0;
            *(__half2*)(g_oh + (size_t)(row + 8) * EMBED + h * HDIM + d) = h1;
        }
    }
}

// ---------------------------------------------------------------------------
extern "C" void kernel_launch(void* const* d_in, const int* in_sizes, int n_in,
                              void* d_out, int out_size)
{
    const float* x   = (const float*)d_in[0];
    const float* Wq  = (const float*)d_in[1];
    const float* bq  = (const float*)d_in[2];
    const float* Wkv = (const float*)d_in[3];
    const float* bkv = (const float*)d_in[4];
    const float* Wo  = (const float*)d_in[5];
    float* out = (float*)d_out;

    __half *xh, *wh, *woh, *oh;
    cudaGetSymbolAddress((void**)&xh,  g_xh);
    cudaGetSymbolAddress((void**)&wh,  g_wh);
    cudaGetSymbolAddress((void**)&woh, g_woh);
    cudaGetSymbolAddress((void**)&oh,  g_oh);

    const int GEMM_SMEM = 110592;   // 3 stages x 36864 (also covers epilogue Cs)
    cudaFuncSetAttribute(gemm_h<0>, cudaFuncAttributeMaxDynamicSharedMemorySize, GEMM_SMEM);
    cudaFuncSetAttribute(gemm_h<1>, cudaFuncAttributeMaxDynamicSharedMemorySize, GEMM_SMEM);
    cudaFuncSetAttribute(attn_h, cudaFuncAttributeMaxDynamicSharedMemorySize, AT_SMEM);

    // 0) conversions + rope table + stacked bias (single launch)
    {
        int total = (NTOK * EMBED + 2 * EMBED * EMBED + KVDIM * EMBED) / 4
                  + SEQ * 64 + QKVN;
        prep_all<<<(total + 255) / 256, 256>>>((const float4*)x, (const float4*)Wq,
                                               (const float4*)Wkv, (const float4*)Wo,
                                               bq, bkv);
    }
    // 1) fused qkv GEMM + bias + RoPE + repack -> g_qh/g_kh/g_vh directly
    gemm_h<1><<<dim3(QKVN/128, NTOK/128), 256, GEMM_SMEM>>>(xh, wh, nullptr, nullptr,
                                                            NTOK, QKVN, EMBED);
    // 2) flash attention -> g_oh  (128 threads, 2 CTAs/SM)
    attn_h<<<dim3(SEQ/128, NHEADS, BATCH), 128, AT_SMEM>>>();
    // 3) out = o @ Wo^T  (fp32 out)
    gemm_h<0><<<dim3(EMBED/128, NTOK/128), 256, GEMM_SMEM>>>(oh, woh, nullptr, out,
                                                             NTOK, EMBED, EMBED);
}